// round 12
// baseline (speedup 1.0000x reference)
#include <cuda_runtime.h>
#include <math.h>
#include <stdint.h>

typedef unsigned long long ull;

// Problem constants
constexpr int S_   = 128;   // sequence length
constexpr int B_   = 64;    // batch
constexpr int E_   = 256;   // embedding dim
constexpr int H_   = 256;   // hidden
constexpr int G4_  = 1024;  // 4*H (gates)
constexpr int HID_ = 30;    // attention hidden
constexpr int NCTA_DIR = 64;   // CTAs per direction in persistent step kernel
constexpr int SB_  = S_ * B_;  // 8192

// Scratch (static device globals — no runtime allocation)
__device__ int   g_ctok[SB_];                // batch-reversed concepts
__device__ float g_embT[E_ * SB_];           // [e][t*B+b]   (fwd x-data)
__device__ float g_embTr[E_ * SB_];          // [e][t*B+b]   (bwd x-data, pre-reversed)
__device__ float g_WT[4][E_ * G4_];          // [e][1024]: 0=Wih_f 1=Wih_b 2=Whh_f 3=Whh_b
__device__ float g_h[2 * S_ * B_ * H_];      // [dir][t][b][k]  (for K4)
__device__ float g_hT[2][2][H_][B_];         // ping-pong [dir][parity][k][b]
__device__ int   g_bar[2 * S_];              // grid-barrier arrival counters
__device__ float g_U[B_ * S_ * HID_];        // u = enc @ Ua^T
__device__ float g_Wt[B_ * HID_ * S_];       // w transposed: [b][k][s]

// fast activations: MUFU-based, rel err ~2e-7 (budget is 1e-3)
__device__ __forceinline__ float fsig(float x)  { return 1.0f / (1.0f + __expf(-x)); }
__device__ __forceinline__ float ftanh(float x) { return 2.0f / (1.0f + __expf(-2.0f * x)) - 1.0f; }

__device__ __forceinline__ void ffma2(ull& d, ull a, ull b) {
    asm("fma.rn.f32x2 %0, %1, %2, %0;" : "+l"(d) : "l"(a), "l"(b));
}
__device__ __forceinline__ ull pack2(float lo, float hi) {
    ull r; asm("mov.b64 %0, {%1, %2};" : "=l"(r) : "f"(lo), "f"(hi)); return r;
}
__device__ __forceinline__ float2 unpack2(ull v) {
    float2 r; asm("mov.b64 {%0, %1}, %2;" : "=f"(r.x), "=f"(r.y) : "l"(v)); return r;
}
// L1-bypassing 16B load (h produced by other CTAs within this launch)
__device__ __forceinline__ void ldcg128(ull& x, ull& y, const float* p) {
    asm volatile("ld.global.cg.v2.u64 {%0, %1}, [%2];" : "=l"(x), "=l"(y) : "l"(p));
}
// read-only L1-cached 16B load (data written before this launch)
__device__ __forceinline__ void ldnc128(ull& x, ull& y, const float* p) {
    asm("ld.global.nc.v2.u64 {%0, %1}, [%2];" : "=l"(x), "=l"(y) : "l"(p));
}
__device__ __forceinline__ void stcg32(float* p, float v) {
    asm volatile("st.global.cg.f32 [%0], %1;" :: "l"(p), "f"(v));
}

// ---------------------------------------------------------------------------
// K0: zero the grid-barrier counters
// ---------------------------------------------------------------------------
__global__ void k_zero_bar() {
    if (threadIdx.x < 2 * S_) g_bar[threadIdx.x] = 0;
}

// ---------------------------------------------------------------------------
// K0b: batch-reversed token matrix  g_ctok[t*B+b] = concepts[rev(t,b)*B+b]
// ---------------------------------------------------------------------------
__global__ void k_revtok(const int* __restrict__ concepts, const int* __restrict__ lens) {
    int idx = blockIdx.x * 256 + threadIdx.x;
    if (idx >= SB_) return;
    int t = idx >> 6, b = idx & 63;
    int L = lens[b];
    int rr = (t < L) ? (L - 1 - t) : t;
    g_ctok[idx] = concepts[rr * B_ + b];
}

// ---------------------------------------------------------------------------
// K1: fused gather + transpose:  dst[e][m] = table[toks[m]][e]
//     grid (E/32, SB/32), block (32,8).  Coalesced both sides.
// ---------------------------------------------------------------------------
__global__ void k_gatherT(const int* __restrict__ toks,
                          const float* __restrict__ table,
                          float* __restrict__ dst) {
    __shared__ float tile[32][33];
    int e0 = blockIdx.x * 32, m0 = blockIdx.y * 32;
    int tx = threadIdx.x, ty = threadIdx.y;
#pragma unroll
    for (int i = 0; i < 4; i++) {
        int m = m0 + ty + i * 8;
        int tok = toks[m];
        tile[ty + i * 8][tx] = table[(size_t)tok * E_ + e0 + tx];
    }
    __syncthreads();
#pragma unroll
    for (int i = 0; i < 4; i++)
        dst[(size_t)(e0 + ty + i * 8) * SB_ + m0 + tx] = tile[tx][ty + i * 8];
}

// ---------------------------------------------------------------------------
// K1b: all 4 weight transposes in one launch (blockIdx.z selects matrix).
//      src [1024][256] row-major -> g_WT[z][e][1024]
// ---------------------------------------------------------------------------
__global__ void k_wtrans(const float* __restrict__ w0, const float* __restrict__ w1,
                         const float* __restrict__ w2, const float* __restrict__ w3) {
    __shared__ float tile[32][33];
    const float* src = (blockIdx.z == 0) ? w0 : (blockIdx.z == 1) ? w1
                      : (blockIdx.z == 2) ? w2 : w3;
    float* dst = &g_WT[blockIdx.z][0];
    int eb = blockIdx.x * 32, mb = blockIdx.y * 32;   // e-tile, row-tile
    int tx = threadIdx.x, ty = threadIdx.y;
#pragma unroll
    for (int i = 0; i < 4; i++)
        tile[ty + i * 8][tx] = src[(size_t)(mb + ty + i * 8) * E_ + eb + tx];
    __syncthreads();
#pragma unroll
    for (int i = 0; i < 4; i++)
        dst[(size_t)(eb + ty + i * 8) * G4_ + mb + tx] = tile[tx][ty + i * 8];
}

// ---------------------------------------------------------------------------
// K3: persistent BiLSTM recurrence WITH FUSED x-projection.
//     Grid = 128 CTAs (64/dir), 512 thr.  CTA owns channels j0..j0+3.
//     Threads: ks 0..3 = h-GEMM warps (k-slices of 64 over Whh·h),
//              ks 4..7 = x-GEMM warps (e-slices of 64 over Wih·x).
//     The x-GEMM for step t+1 runs INSIDE the barrier arrive->poll window
//     (no cross-CTA dependency), hiding it behind skew/detection.
//     Weights read via ld.global.nc (L1-resident 32KB/CTA); no weight smem.
//     Barrier = R10's proven tid0 atomic arrive + tid0 poll.
// ---------------------------------------------------------------------------
__global__ __launch_bounds__(512, 1) void k_steps(const int* __restrict__ lens,
                                                  const float* __restrict__ b_f,
                                                  const float* __restrict__ b_b) {
    __shared__ float part_s[8][16][64];   // k-slice partial gates  32 KB

    const int tid = threadIdx.x;
    const int dir = blockIdx.x >> 6;
    const int cb  = blockIdx.x & 63;
    const int j0  = cb * 4;

    // GEMM ids: lane = rq(4) x bq_low(8); bq octet from half-warp bit
    const int ks = tid >> 6;               // 0..7
    const int rq = (tid >> 3) & 3;         // row quad 0..3  (= gate index)
    const int bq = (((tid >> 5) & 1) << 3) | (tid & 7);
    const int r0 = rq * 4;
    const int b0 = bq * 4;
    const int kbase = (ks & 3) * 64;       // 64-wide slice
    const bool hside = (ks < 4);

    // weight row quad: global gate rows rq*256 + j0 .. +3 (consecutive)
    const float* __restrict__ wq = (hside ? &g_WT[2 + dir][0] : &g_WT[dir][0])
                                   + (size_t)kbase * G4_ + rq * 256 + j0;
    const float* __restrict__ xq = (dir ? g_embTr : g_embT) + (size_t)kbase * SB_ + b0;

    // pointwise ids (tid<256 == hside warps)
    const bool pw  = (tid < 256);
    const int  pch = tid >> 6;
    const int  pb  = tid & 63;
    float creg = 0.0f;
    float bv0 = 0.f, bv1 = 0.f, bv2 = 0.f, bv3 = 0.f;
    if (pw) {
        const float* bias = dir ? b_b : b_f;
        bv0 = __ldg(bias + 0 * 256 + j0 + pch);
        bv1 = __ldg(bias + 1 * 256 + j0 + pch);
        bv2 = __ldg(bias + 2 * 256 + j0 + pch);
        bv3 = __ldg(bias + 3 * 256 + j0 + pch);
    }

    float* __restrict__ houtB = g_h + (size_t)dir * S_ * B_ * H_;
    int* barp = g_bar + dir * S_;

    // ---- x-GEMM helper (x warps only): gates_x for step t into part_s[ks]
    auto do_x = [&](int t) {
        ull a00 = 0, a01 = 0, a10 = 0, a11 = 0, a20 = 0, a21 = 0, a30 = 0, a31 = 0;
        const float* dp = xq + (size_t)t * 64;
#pragma unroll 8
        for (int kk = 0; kk < 64; ++kk) {
            ull hx, hy;
            ldnc128(hx, hy, dp + (size_t)kk * SB_);
            float4 wv = __ldg(reinterpret_cast<const float4*>(wq + (size_t)kk * G4_));
            ull w0 = pack2(wv.x, wv.x), w1 = pack2(wv.y, wv.y);
            ull w2 = pack2(wv.z, wv.z), w3 = pack2(wv.w, wv.w);
            ffma2(a00, w0, hx); ffma2(a01, w0, hy);
            ffma2(a10, w1, hx); ffma2(a11, w1, hy);
            ffma2(a20, w2, hx); ffma2(a21, w2, hy);
            ffma2(a30, w3, hx); ffma2(a31, w3, hy);
        }
        float2 l0 = unpack2(a00), h0 = unpack2(a01);
        float2 l1 = unpack2(a10), h1 = unpack2(a11);
        float2 l2 = unpack2(a20), h2v = unpack2(a21);
        float2 l3 = unpack2(a30), h3 = unpack2(a31);
        *reinterpret_cast<float4*>(&part_s[ks][r0 + 0][b0]) = make_float4(l0.x, l0.y, h0.x, h0.y);
        *reinterpret_cast<float4*>(&part_s[ks][r0 + 1][b0]) = make_float4(l1.x, l1.y, h1.x, h1.y);
        *reinterpret_cast<float4*>(&part_s[ks][r0 + 2][b0]) = make_float4(l2.x, l2.y, h2v.x, h2v.y);
        *reinterpret_cast<float4*>(&part_s[ks][r0 + 3][b0]) = make_float4(l3.x, l3.y, h3.x, h3.y);
    };

    // prologue: x for t=0 (no barrier dependency)
    if (!hside) do_x(0);
    __syncthreads();

    for (int t = 0; t < S_; ++t) {
        // ---- h-GEMM for step t (h warps; barrier for h(t-1) passed last iter)
        if (t > 0 && hside) {
            ull a00 = 0, a01 = 0, a10 = 0, a11 = 0, a20 = 0, a21 = 0, a30 = 0, a31 = 0;
            const float* hsrc = &g_hT[dir][(t - 1) & 1][0][0] + (size_t)kbase * 64 + b0;
#pragma unroll 8
            for (int kk = 0; kk < 64; ++kk) {
                ull hx, hy;
                ldcg128(hx, hy, hsrc + kk * 64);
                float4 wv = __ldg(reinterpret_cast<const float4*>(wq + (size_t)kk * G4_));
                ull w0 = pack2(wv.x, wv.x), w1 = pack2(wv.y, wv.y);
                ull w2 = pack2(wv.z, wv.z), w3 = pack2(wv.w, wv.w);
                ffma2(a00, w0, hx); ffma2(a01, w0, hy);
                ffma2(a10, w1, hx); ffma2(a11, w1, hy);
                ffma2(a20, w2, hx); ffma2(a21, w2, hy);
                ffma2(a30, w3, hx); ffma2(a31, w3, hy);
            }
            float2 l0 = unpack2(a00), h0 = unpack2(a01);
            float2 l1 = unpack2(a10), h1 = unpack2(a11);
            float2 l2 = unpack2(a20), h2v = unpack2(a21);
            float2 l3 = unpack2(a30), h3 = unpack2(a31);
            *reinterpret_cast<float4*>(&part_s[ks][r0 + 0][b0]) = make_float4(l0.x, l0.y, h0.x, h0.y);
            *reinterpret_cast<float4*>(&part_s[ks][r0 + 1][b0]) = make_float4(l1.x, l1.y, h1.x, h1.y);
            *reinterpret_cast<float4*>(&part_s[ks][r0 + 2][b0]) = make_float4(l2.x, l2.y, h2v.x, h2v.y);
            *reinterpret_cast<float4*>(&part_s[ks][r0 + 3][b0]) = make_float4(l3.x, l3.y, h3.x, h3.y);
        }
        __syncthreads();

        // ---- pointwise: gates = Σ parts + bias
        if (pw) {
            float gv0 = bv0, gv1 = bv1, gv2 = bv2, gv3 = bv3;
            const int s0 = (t > 0) ? 0 : 4;
#pragma unroll
            for (int s = 0; s < 8; ++s) {
                if (s >= s0) {
                    gv0 += part_s[s][0 * 4 + pch][pb];
                    gv1 += part_s[s][1 * 4 + pch][pb];
                    gv2 += part_s[s][2 * 4 + pch][pb];
                    gv3 += part_s[s][3 * 4 + pch][pb];
                }
            }
            float cn = fsig(gv1) * creg + fsig(gv0) * ftanh(gv2);
            float hn = fsig(gv3) * ftanh(cn);
            creg = cn;
            houtB[(size_t)t * B_ * H_ + pb * H_ + j0 + pch] = hn;
            stcg32(&g_hT[dir][t & 1][j0 + pch][pb], hn);
        }

        if (t < S_ - 1) {
            __syncthreads();                 // h(t) stores + part_s reads done
            // arrive FIRST (release orders the g_hT stores)
            if (tid == 0)
                asm volatile("red.release.gpu.global.add.s32 [%0], 1;" :: "l"(barp + t) : "memory");

            // x-GEMM for t+1 — hidden behind peers' arrival + detection
            if (!hside) do_x(t + 1);

            // wait
            if (tid == 0) {
                int guard = 1 << 20;
                int v;
                do {
                    asm volatile("ld.acquire.gpu.global.s32 %0, [%1];" : "=r"(v) : "l"(barp + t) : "memory");
                } while (v < NCTA_DIR && --guard);
            }
            __syncthreads();
        }
    }
}

// ---------------------------------------------------------------------------
// K4: u/w projections.  Block = (b, s-group of 8), 512 threads.
// ---------------------------------------------------------------------------
__global__ __launch_bounds__(512) void k_uw(const int* __restrict__ lens,
                                            const float* __restrict__ Ua,
                                            const float* __restrict__ Wa) {
    __shared__ float enc_s[8][516];

    const int b  = blockIdx.x;
    const int sg = blockIdx.y;
    const int tid = threadIdx.x;
    const int L = lens[b];

    {
        int lr = tid >> 6;             // local s row 0..7
        int lc = (tid & 63) * 8;       // col 0..504 step 8
        int s_row = sg * 8 + lr;
        bool valid = (s_row < L);
        int ridx = valid ? (L - 1 - s_row) : s_row;
        const float* src = (lc < 256)
            ? g_h + (size_t)s_row * B_ * H_ + b * H_ + lc
            : g_h + (size_t)S_ * B_ * H_ + (size_t)ridx * B_ * H_ + b * H_ + (lc - 256);
        float4 v0 = make_float4(0.f, 0.f, 0.f, 0.f);
        float4 v1 = v0;
        if (valid) {
            v0 = *reinterpret_cast<const float4*>(src);
            v1 = *reinterpret_cast<const float4*>(src + 4);
        }
        *reinterpret_cast<float4*>(&enc_s[lr][lc])     = v0;
        *reinterpret_cast<float4*>(&enc_s[lr][lc + 4]) = v1;
    }
    __syncthreads();

    const int row = tid >> 3;
    const int sl  = tid & 7;
    if (row < 2 * HID_) {
        const float* __restrict__ Wrow =
            (row < HID_) ? (Ua + (size_t)row * 2 * H_) : (Wa + (size_t)(row - HID_) * 2 * H_);
        float acc = 0.f;
#pragma unroll 8
        for (int k = 0; k < 2 * H_; k += 4) {
            float4 wv = *reinterpret_cast<const float4*>(Wrow + k);
            float4 ev = *reinterpret_cast<const float4*>(&enc_s[sl][k]);
            acc += wv.x * ev.x + wv.y * ev.y + wv.z * ev.z + wv.w * ev.w;
        }
        int s = sg * 8 + sl;
        if (row < HID_)
            g_U[((size_t)b * S_ + s) * HID_ + row] = acc;
        else
            g_Wt[(size_t)b * HID_ * S_ + (size_t)(row - HID_) * S_ + s] = acc;
    }
}

// ---------------------------------------------------------------------------
// K5: scores + predictions (MUFU tanh).
// ---------------------------------------------------------------------------
__global__ void k_scores(const float* __restrict__ va, float* __restrict__ out) {
    const int i = blockIdx.x;
    const int b = blockIdx.y;
    const int j = threadIdx.x;   // 128

    __shared__ float u_s[HID_];
    __shared__ float va_s[HID_];
    if (j < HID_) {
        u_s[j]  = g_U[((size_t)b * S_ + i) * HID_ + j];
        va_s[j] = va[j];
    }
    __syncthreads();

    const float* __restrict__ Wb = g_Wt + (size_t)b * HID_ * S_;
    float acc = 0.f;
#pragma unroll
    for (int k = 0; k < HID_; k++) {
        float wv = Wb[k * S_ + j];
        acc += ftanh(u_s[k] + wv) * va_s[k];
    }
    size_t idx = ((size_t)b * S_ + i) * S_ + j;
    out[idx] = acc;
    out[(size_t)B_ * S_ * S_ + idx] = (acc >= 0.0f) ? 1.0f : 0.0f;
}

// ---------------------------------------------------------------------------
extern "C" void kernel_launch(void* const* d_in, const int* in_sizes, int n_in,
                              void* d_out, int out_size) {
    const int*   concepts = (const int*)d_in[0];
    const int*   lens     = (const int*)d_in[1];
    const float* emb      = (const float*)d_in[2];
    const float* Wih_f    = (const float*)d_in[3];
    const float* Whh_f    = (const float*)d_in[4];
    const float* b_f      = (const float*)d_in[5];
    const float* Wih_b    = (const float*)d_in[6];
    const float* Whh_b    = (const float*)d_in[7];
    const float* b_b      = (const float*)d_in[8];
    const float* Ua       = (const float*)d_in[9];
    const float* Wa       = (const float*)d_in[10];
    const float* va       = (const float*)d_in[11];
    float* out = (float*)d_out;

    int*   ctok_p  = nullptr;
    float* embT_p  = nullptr;
    float* embTr_p = nullptr;
    cudaGetSymbolAddress((void**)&ctok_p,  g_ctok);
    cudaGetSymbolAddress((void**)&embT_p,  g_embT);
    cudaGetSymbolAddress((void**)&embTr_p, g_embTr);

    k_zero_bar<<<1, 256>>>();
    k_revtok<<<SB_ / 256, 256>>>(concepts, lens);
    k_gatherT<<<dim3(E_ / 32, SB_ / 32), dim3(32, 8)>>>(concepts, emb, embT_p);
    k_gatherT<<<dim3(E_ / 32, SB_ / 32), dim3(32, 8)>>>(ctok_p, emb, embTr_p);
    k_wtrans<<<dim3(E_ / 32, G4_ / 32, 4), dim3(32, 8)>>>(Wih_f, Wih_b, Whh_f, Whh_b);
    k_steps<<<2 * NCTA_DIR, 512>>>(lens, b_f, b_b);      // launch index 5 -> profiled
    k_uw<<<dim3(B_, S_ / 8), 512>>>(lens, Ua, Wa);
    k_scores<<<dim3(S_, B_), 128>>>(va, out);
}

// round 14
// speedup vs baseline: 1.3855x; 1.3855x over previous
#include <cuda_runtime.h>
#include <math.h>
#include <stdint.h>

typedef unsigned long long ull;

// Problem constants
constexpr int S_   = 128;   // sequence length
constexpr int B_   = 64;    // batch
constexpr int E_   = 256;   // embedding dim
constexpr int H_   = 256;   // hidden
constexpr int G4_  = 1024;  // 4*H (gates)
constexpr int HID_ = 30;    // attention hidden
constexpr int NCTA_DIR = 64;   // CTAs per direction in persistent step kernel

// Scratch (static device globals — no runtime allocation)
__device__ float g_emb[S_ * B_ * E_];        // (t,b,e)
__device__ float g_embT[E_ * S_ * B_];       // transposed: [e][t*B+b]
__device__ float g_WihT[2 * E_ * G4_];       // transposed Wih per dir: [k][n]
__device__ float g_X[2 * S_ * B_ * G4_];     // x-projections per dir, bias folded in
__device__ float g_h[2 * S_ * B_ * H_];      // [dir][t][b][k]  (for K4)
__device__ float g_hT[2][2][H_][B_];         // ping-pong [dir][parity][k][b]
__device__ int   g_bar[2 * S_];              // grid-barrier arrival counters
__device__ float g_U[B_ * S_ * HID_];        // u = enc @ Ua^T
__device__ float g_Wt[B_ * HID_ * S_];       // w transposed: [b][k][s]

// fast activations: MUFU-based, rel err ~2e-7 (budget is 1e-3)
__device__ __forceinline__ float fsig(float x)  { return 1.0f / (1.0f + __expf(-x)); }
__device__ __forceinline__ float ftanh(float x) { return 2.0f / (1.0f + __expf(-2.0f * x)) - 1.0f; }

// pure (non-volatile) packed fp32 math — scheduler may move these freely
__device__ __forceinline__ void ffma2(ull& d, ull a, ull b) {
    asm("fma.rn.f32x2 %0, %1, %2, %0;" : "+l"(d) : "l"(a), "l"(b));
}
__device__ __forceinline__ ull pack2(float lo, float hi) {
    ull r; asm("mov.b64 %0, {%1, %2};" : "=l"(r) : "f"(lo), "f"(hi)); return r;
}
__device__ __forceinline__ float2 unpack2(ull v) {
    float2 r; asm("mov.b64 {%0, %1}, %2;" : "=f"(r.x), "=f"(r.y) : "l"(v)); return r;
}
// L1-bypassing 16B load (h produced by other CTAs within this launch)
__device__ __forceinline__ void ldcg128(ull& x, ull& y, const float* p) {
    asm volatile("ld.global.cg.v2.u64 {%0, %1}, [%2];" : "=l"(x), "=l"(y) : "l"(p));
}
__device__ __forceinline__ void stcg32(float* p, float v) {
    asm volatile("st.global.cg.f32 [%0], %1;" :: "l"(p), "f"(v));
}
__device__ __forceinline__ void cp16(uint32_t smem_dst, const void* gsrc) {
    asm volatile("cp.async.cg.shared.global [%0], [%1], 16;" :: "r"(smem_dst), "l"(gsrc) : "memory");
}

// ---------------------------------------------------------------------------
// K0: zero the grid-barrier counters (stream-ordered before k_steps)
// ---------------------------------------------------------------------------
__global__ void k_zero_bar() {
    if (threadIdx.x < 2 * S_) g_bar[threadIdx.x] = 0;
}

// ---------------------------------------------------------------------------
// K1: embedding gather.  grid = S*B blocks, 64 threads (float4 row copy)
// ---------------------------------------------------------------------------
__global__ void k_gather(const int* __restrict__ concepts,
                         const float* __restrict__ table) {
    int tb  = blockIdx.x;                      // t*B + b
    int tok = concepts[tb];
    const float4* src = reinterpret_cast<const float4*>(table + (size_t)tok * E_);
    float4*       dst = reinterpret_cast<float4*>(g_emb + (size_t)tb * E_);
    dst[threadIdx.x] = src[threadIdx.x];
}

// ---------------------------------------------------------------------------
// K1b: tiled transpose  src[M][N] -> dst[N][M]   (M,N multiples of 32)
// ---------------------------------------------------------------------------
__global__ void k_transpose(const float* __restrict__ src, float* __restrict__ dst,
                            int M, int N) {
    __shared__ float t[32][33];
    int nb = blockIdx.x * 32, mb = blockIdx.y * 32;
    int tx = threadIdx.x, ty = threadIdx.y;   // (32, 8)
#pragma unroll
    for (int i = 0; i < 4; i++)
        t[ty + i * 8][tx] = src[(size_t)(mb + ty + i * 8) * N + nb + tx];
    __syncthreads();
#pragma unroll
    for (int i = 0; i < 4; i++)
        dst[(size_t)(nb + ty + i * 8) * M + mb + tx] = t[tx][ty + i * 8];
}

// ---------------------------------------------------------------------------
// K2: x-projection GEMM  X[dir] = emb @ Wih[dir]^T + b[dir]
//     M=8192, N=1024, K=256.  BM=128, BN=64, BK=16, 256 thr, 8x4 microtile,
//     packed f32x2 FMA, cp.async double buffer.  BN=64 halves accumulator
//     registers (acc2[8][2]) -> ~3 CTAs/SM for cross-wave overlap.
// ---------------------------------------------------------------------------
__global__ __launch_bounds__(256) void k_xgemm(const float* __restrict__ b_f,
                                               const float* __restrict__ b_b) {
    const int dir = blockIdx.z;
    const float* __restrict__ AT   = g_embT;                      // [k][8192]
    const float* __restrict__ BT   = g_WihT + (size_t)dir * E_ * G4_;  // [k][1024]
    const float* __restrict__ bias = dir ? b_b : b_f;
    float* __restrict__ Xout = g_X + (size_t)dir * S_ * B_ * G4_;

    __shared__ float As[2][16][132];   // [stage][k][m]  8448 B/stage
    __shared__ float Bs[2][16][68];    // [stage][k][n]  4352 B/stage

    const int m0  = blockIdx.x * 128;
    const int n0  = blockIdx.y * 64;
    const int tid = threadIdx.x;
    const int tx  = tid & 15;       // -> n quad (4 wide)
    const int ty  = tid >> 4;       // -> m oct (8 wide)

    const uint32_t as_sa = (uint32_t)__cvta_generic_to_shared(&As[0][0][0]);
    const uint32_t bs_sa = (uint32_t)__cvta_generic_to_shared(&Bs[0][0][0]);
    // A: 512 quads/stage -> 2 per thread (q=tid, tid+256: same col, k+8)
    const int rA = tid >> 5;            // k row 0..7
    const int cA = (tid & 31) * 4;      // m col 0..124
    // B: 256 quads/stage -> 1 per thread
    const int rB = tid >> 4;            // k row 0..15
    const int cB = (tid & 15) * 4;      // n col 0..60

    auto load_stage = [&](int st, int kc) {
        uint32_t abase = as_sa + st * (16 * 132 * 4);
        uint32_t bbase = bs_sa + st * (16 * 68 * 4);
        cp16(abase + (rA * 132 + cA) * 4,       AT + (size_t)(kc + rA) * 8192 + m0 + cA);
        cp16(abase + ((rA + 8) * 132 + cA) * 4, AT + (size_t)(kc + rA + 8) * 8192 + m0 + cA);
        cp16(bbase + (rB * 68 + cB) * 4,        BT + (size_t)(kc + rB) * 1024 + n0 + cB);
        asm volatile("cp.async.commit_group;" ::: "memory");
    };

    ull acc2[8][2];
#pragma unroll
    for (int i = 0; i < 8; i++) { acc2[i][0] = 0ull; acc2[i][1] = 0ull; }

    load_stage(0, 0);
#pragma unroll 1
    for (int it = 0; it < 16; ++it) {
        const int cur = it & 1;
        if (it < 15) load_stage(cur ^ 1, (it + 1) * 16);
        if (it < 15) asm volatile("cp.async.wait_group 1;" ::: "memory");
        else         asm volatile("cp.async.wait_group 0;" ::: "memory");
        __syncthreads();
#pragma unroll
        for (int k = 0; k < 16; k++) {
            float4 a0 = *reinterpret_cast<const float4*>(&As[cur][k][ty * 8]);
            float4 a1 = *reinterpret_cast<const float4*>(&As[cur][k][ty * 8 + 4]);
            ulonglong2 bb = *reinterpret_cast<const ulonglong2*>(&Bs[cur][k][tx * 4]);
            float av[8] = { a0.x, a0.y, a0.z, a0.w, a1.x, a1.y, a1.z, a1.w };
#pragma unroll
            for (int i = 0; i < 8; i++) {
                ull ap = pack2(av[i], av[i]);
                ffma2(acc2[i][0], ap, bb.x);
                ffma2(acc2[i][1], ap, bb.y);
            }
        }
        __syncthreads();
    }

    // epilogue: add bias, one float4 store per m-row
    float bv0 = bias[n0 + tx * 4 + 0];
    float bv1 = bias[n0 + tx * 4 + 1];
    float bv2 = bias[n0 + tx * 4 + 2];
    float bv3 = bias[n0 + tx * 4 + 3];
#pragma unroll
    for (int i = 0; i < 8; i++) {
        int m = m0 + ty * 8 + i;
        float2 e0 = unpack2(acc2[i][0]);
        float2 e1 = unpack2(acc2[i][1]);
        float4 o;
        o.x = e0.x + bv0; o.y = e0.y + bv1;
        o.z = e1.x + bv2; o.w = e1.y + bv3;
        *reinterpret_cast<float4*>(Xout + (size_t)m * G4_ + n0 + tx * 4) = o;
    }
}

// ---------------------------------------------------------------------------
// K3: persistent BiLSTM recurrence — R10 verbatim (proven 516us form).
// ---------------------------------------------------------------------------
__global__ __launch_bounds__(512, 1) void k_steps(const int* __restrict__ lens,
                                                  const float* __restrict__ Whh_f,
                                                  const float* __restrict__ Whh_b) {
    __shared__ float w_s[256][16];        // [k][row]  16 KB (transposed Whh slice)
    __shared__ float part_s[8][16][64];   // k-slice partial gates  32 KB

    const int tid = threadIdx.x;
    const int dir = blockIdx.x >> 6;
    const int cb  = blockIdx.x & 63;
    const int j0  = cb * 4;
    const float* __restrict__ Whh = dir ? Whh_b : Whh_f;
    const float* __restrict__ X   = g_X + (size_t)dir * S_ * B_ * G4_;

    {
        int row = tid >> 5;                 // 0..15 (= gate*4 + ch)
        int gg  = row >> 2, ch = row & 3;
        int grw = gg * H_ + j0 + ch;
        const float* src = Whh + (size_t)grw * H_ + (tid & 31) * 8;
#pragma unroll
        for (int u = 0; u < 8; u += 4) {
            float4 v = *reinterpret_cast<const float4*>(src + u);
            int k0 = (tid & 31) * 8 + u;
            w_s[k0 + 0][row] = v.x;
            w_s[k0 + 1][row] = v.y;
            w_s[k0 + 2][row] = v.z;
            w_s[k0 + 3][row] = v.w;
        }
    }

    const int ks = tid >> 6;               // k-slice 0..7 (32 k each)
    const int rq = (tid >> 3) & 3;         // row quad 0..3
    const int bq = (((tid >> 5) & 1) << 3) | (tid & 7);   // batch quad 0..15
    const int r0 = rq * 4;
    const int b0 = bq * 4;
    const int kbase = ks * 32;

    const bool pw  = (tid < 256);
    const int  pch = tid >> 6;         // 0..3 channel within CTA (valid when pw)
    const int  pb  = tid & 63;         // batch
    const int  Lp  = pw ? __ldg(lens + pb) : 0;
    float creg = 0.0f;

    float* __restrict__ houtB = g_h + (size_t)dir * S_ * B_ * H_;
    int* barp = g_bar + dir * S_;

    float xg0 = 0.f, xg1 = 0.f, xg2 = 0.f, xg3 = 0.f;
    if (pw) {
        int m;
        if (dir == 0) m = pb;
        else { int rr = (0 < Lp) ? (Lp - 1) : 0; m = rr * B_ + pb; }
        const float* Xm = X + (size_t)m * G4_ + j0 + pch;
        xg0 = Xm[0 * H_]; xg1 = Xm[1 * H_]; xg2 = Xm[2 * H_]; xg3 = Xm[3 * H_];
    }
    __syncthreads();   // w_s ready

    for (int t = 0; t < S_; ++t) {
        if (t > 0) {
            ull a00 = 0, a01 = 0, a10 = 0, a11 = 0, a20 = 0, a21 = 0, a30 = 0, a31 = 0;
            const float* hsrc = &g_hT[dir][(t - 1) & 1][0][0] + (size_t)kbase * 64 + b0;
#pragma unroll 8
            for (int kk = 0; kk < 32; ++kk) {
                ull hx, hy;
                ldcg128(hx, hy, hsrc + kk * 64);
                float4 wv = *reinterpret_cast<const float4*>(&w_s[kbase + kk][r0]);
                ull w0 = pack2(wv.x, wv.x), w1 = pack2(wv.y, wv.y);
                ull w2 = pack2(wv.z, wv.z), w3 = pack2(wv.w, wv.w);
                ffma2(a00, w0, hx); ffma2(a01, w0, hy);
                ffma2(a10, w1, hx); ffma2(a11, w1, hy);
                ffma2(a20, w2, hx); ffma2(a21, w2, hy);
                ffma2(a30, w3, hx); ffma2(a31, w3, hy);
            }
            float2 l0 = unpack2(a00), h0 = unpack2(a01);
            float2 l1 = unpack2(a10), h1 = unpack2(a11);
            float2 l2 = unpack2(a20), h2v = unpack2(a21);
            float2 l3 = unpack2(a30), h3 = unpack2(a31);
            *reinterpret_cast<float4*>(&part_s[ks][r0 + 0][b0]) = make_float4(l0.x, l0.y, h0.x, h0.y);
            *reinterpret_cast<float4*>(&part_s[ks][r0 + 1][b0]) = make_float4(l1.x, l1.y, h1.x, h1.y);
            *reinterpret_cast<float4*>(&part_s[ks][r0 + 2][b0]) = make_float4(l2.x, l2.y, h2v.x, h2v.y);
            *reinterpret_cast<float4*>(&part_s[ks][r0 + 3][b0]) = make_float4(l3.x, l3.y, h3.x, h3.y);
            __syncthreads();
        }

        if (pw) {
            float gv0 = xg0, gv1 = xg1, gv2 = xg2, gv3 = xg3;
            if (t > 0) {
#pragma unroll
                for (int s = 0; s < 8; ++s) {
                    gv0 += part_s[s][0 * 4 + pch][pb];
                    gv1 += part_s[s][1 * 4 + pch][pb];
                    gv2 += part_s[s][2 * 4 + pch][pb];
                    gv3 += part_s[s][3 * 4 + pch][pb];
                }
            }
            float cn = fsig(gv1) * creg + fsig(gv0) * ftanh(gv2);
            float hn = fsig(gv3) * ftanh(cn);
            creg = cn;
            houtB[(size_t)t * B_ * H_ + pb * H_ + j0 + pch] = hn;
            stcg32(&g_hT[dir][t & 1][j0 + pch][pb], hn);
        }

        if (t < S_ - 1) {
            __syncthreads();                 // h(t) stores done CTA-wide
            if (tid == 0)
                asm volatile("red.release.gpu.global.add.s32 [%0], 1;" :: "l"(barp + t) : "memory");

            if (pw) {
                int tn = t + 1;
                int m;
                if (dir == 0) m = tn * B_ + pb;
                else { int rr = (tn < Lp) ? (Lp - 1 - tn) : tn; m = rr * B_ + pb; }
                const float* Xm = X + (size_t)m * G4_ + j0 + pch;
                xg0 = Xm[0 * H_]; xg1 = Xm[1 * H_]; xg2 = Xm[2 * H_]; xg3 = Xm[3 * H_];
            }

            if (tid == 0) {
                int guard = 1 << 20;
                int v;
                do {
                    asm volatile("ld.acquire.gpu.global.s32 %0, [%1];" : "=r"(v) : "l"(barp + t) : "memory");
                } while (v < NCTA_DIR && --guard);
            }
            __syncthreads();
        }
    }
}

// ---------------------------------------------------------------------------
// K4: u/w projections.  Block = (b, s-group of 8), 512 threads.
// ---------------------------------------------------------------------------
__global__ __launch_bounds__(512) void k_uw(const int* __restrict__ lens,
                                            const float* __restrict__ Ua,
                                            const float* __restrict__ Wa) {
    __shared__ float enc_s[8][516];

    const int b  = blockIdx.x;
    const int sg = blockIdx.y;
    const int tid = threadIdx.x;
    const int L = lens[b];

    {
        int lr = tid >> 6;             // local s row 0..7
        int lc = (tid & 63) * 8;       // col 0..504 step 8
        int s_row = sg * 8 + lr;
        bool valid = (s_row < L);
        int ridx = valid ? (L - 1 - s_row) : s_row;
        const float* src = (lc < 256)
            ? g_h + (size_t)s_row * B_ * H_ + b * H_ + lc
            : g_h + (size_t)S_ * B_ * H_ + (size_t)ridx * B_ * H_ + b * H_ + (lc - 256);
        float4 v0 = make_float4(0.f, 0.f, 0.f, 0.f);
        float4 v1 = v0;
        if (valid) {
            v0 = *reinterpret_cast<const float4*>(src);
            v1 = *reinterpret_cast<const float4*>(src + 4);
        }
        *reinterpret_cast<float4*>(&enc_s[lr][lc])     = v0;
        *reinterpret_cast<float4*>(&enc_s[lr][lc + 4]) = v1;
    }
    __syncthreads();

    const int row = tid >> 3;
    const int sl  = tid & 7;
    if (row < 2 * HID_) {
        const float* __restrict__ Wrow =
            (row < HID_) ? (Ua + (size_t)row * 2 * H_) : (Wa + (size_t)(row - HID_) * 2 * H_);
        float acc = 0.f;
#pragma unroll 8
        for (int k = 0; k < 2 * H_; k += 4) {
            float4 wv = *reinterpret_cast<const float4*>(Wrow + k);
            float4 ev = *reinterpret_cast<const float4*>(&enc_s[sl][k]);
            acc += wv.x * ev.x + wv.y * ev.y + wv.z * ev.z + wv.w * ev.w;
        }
        int s = sg * 8 + sl;
        if (row < HID_)
            g_U[((size_t)b * S_ + s) * HID_ + row] = acc;
        else
            g_Wt[(size_t)b * HID_ * S_ + (size_t)(row - HID_) * S_ + s] = acc;
    }
}

// ---------------------------------------------------------------------------
// K5: scores + predictions (MUFU tanh).
// ---------------------------------------------------------------------------
__global__ void k_scores(const float* __restrict__ va, float* __restrict__ out) {
    const int i = blockIdx.x;
    const int b = blockIdx.y;
    const int j = threadIdx.x;   // 128

    __shared__ float u_s[HID_];
    __shared__ float va_s[HID_];
    if (j < HID_) {
        u_s[j]  = g_U[((size_t)b * S_ + i) * HID_ + j];
        va_s[j] = va[j];
    }
    __syncthreads();

    const float* __restrict__ Wb = g_Wt + (size_t)b * HID_ * S_;
    float acc = 0.f;
#pragma unroll
    for (int k = 0; k < HID_; k++) {
        float wv = Wb[k * S_ + j];
        acc += ftanh(u_s[k] + wv) * va_s[k];
    }
    size_t idx = ((size_t)b * S_ + i) * S_ + j;
    out[idx] = acc;
    out[(size_t)B_ * S_ * S_ + idx] = (acc >= 0.0f) ? 1.0f : 0.0f;
}

// ---------------------------------------------------------------------------
extern "C" void kernel_launch(void* const* d_in, const int* in_sizes, int n_in,
                              void* d_out, int out_size) {
    const int*   concepts = (const int*)d_in[0];
    const int*   lens     = (const int*)d_in[1];
    const float* emb      = (const float*)d_in[2];
    const float* Wih_f    = (const float*)d_in[3];
    const float* Whh_f    = (const float*)d_in[4];
    const float* b_f      = (const float*)d_in[5];
    const float* Wih_b    = (const float*)d_in[6];
    const float* Whh_b    = (const float*)d_in[7];
    const float* b_b      = (const float*)d_in[8];
    const float* Ua       = (const float*)d_in[9];
    const float* Wa       = (const float*)d_in[10];
    const float* va       = (const float*)d_in[11];
    float* out = (float*)d_out;

    float* embT_p = nullptr;
    float* WihT_p = nullptr;
    float* emb_p  = nullptr;
    cudaGetSymbolAddress((void**)&embT_p, g_embT);
    cudaGetSymbolAddress((void**)&WihT_p, g_WihT);
    cudaGetSymbolAddress((void**)&emb_p,  g_emb);

    k_zero_bar<<<1, 256>>>();
    k_gather<<<S_ * B_, 64>>>(concepts, emb);
    k_transpose<<<dim3(E_ / 32, (S_ * B_) / 32), dim3(32, 8)>>>(emb_p, embT_p, S_ * B_, E_);
    k_transpose<<<dim3(E_ / 32, G4_ / 32), dim3(32, 8)>>>(Wih_f, WihT_p, G4_, E_);
    k_transpose<<<dim3(E_ / 32, G4_ / 32), dim3(32, 8)>>>(Wih_b, WihT_p + E_ * G4_, G4_, E_);
    k_xgemm<<<dim3(64, 16, 2), 256>>>(b_f, b_b);
    k_steps<<<2 * NCTA_DIR, 512>>>(lens, Whh_f, Whh_b);
    k_uw<<<dim3(B_, S_ / 8), 512>>>(lens, Ua, Wa);
    k_scores<<<dim3(S_, B_), 128>>>(va, out);
}